// round 16
// baseline (speedup 1.0000x reference)
#include <cuda_runtime.h>
#include <cuda_bf16.h>
#include <cuda_fp16.h>
#include <math.h>
#include <stdint.h>

#define S_LEN  128
#define B_SZ   32
#define NTOKR  4096      // S*B rows
#define NWE    512
#define D_T    64
#define H_RNN  1024
#define G4     4096      // 4*H
#define NVOCAB 32000

#define A_SCALE       16384.0f          // 2^14: lifts tiny activations into fp16 normal range
#define INV_A_SCALE   6.103515625e-5f
#define LO_SCALE      2048.0f
#define INV_LO_SCALE  4.8828125e-4f

// ------------------- scratch (device globals; no allocs allowed) -------------
__device__ float g_ht[B_SZ * D_T];
__device__ float g_vb[B_SZ * D_T];
__device__ float g_M[B_SZ * D_T * NWE];          // 4MB
__device__ float g_emb[NTOKR * NWE];             // 8MB
__device__ float g_xp0[(size_t)NTOKR * G4];      // 64MB (PERMUTED gate cols)
__device__ float g_xp1g[2][B_SZ * G4];           // ping-pong layer1 input gates (1MB)
__device__ float g_c[2][B_SZ * H_RNN];
__device__ float g_gb0[G4];                      // permuted
__device__ float g_gb1[G4];                      // permuted
// fp16 scratch (g_Ah: emb*2^14 for xp0 A, later decoder A written by layer1;
// g_Bh/g_Bl: Wih0 split for xp0 B, later g_Bh = decoder fp16 B)
__device__ __half g_Ah[(size_t)NTOKR * H_RNN];               // 8MB
__device__ __half g_Bh[(size_t)NVOCAB * H_RNN];              // 62.5MB
__device__ __half g_Bl[(size_t)NVOCAB * H_RNN];              // 62.5MB
// LSTM tensorized state: fp16 split weights (permuted rows), fp16 scaled h/out0
__device__ __half g_W0h[(size_t)G4 * H_RNN];                 // 8MB
__device__ __half g_W0l[(size_t)G4 * H_RNN];
__device__ __half g_W1h[(size_t)G4 * 2048];                  // 16MB ([Whh1|Wih1])
__device__ __half g_W1l[(size_t)G4 * 2048];
__device__ __half g_hs[2][2][B_SZ * H_RNN];                  // h * 2^14
__device__ __half g_o0[(size_t)NTOKR * H_RNN];               // out0 * 2^14, 8MB
// persistent-kernel grid barrier state
__device__ unsigned int g_bar_count;
__device__ unsigned int g_bar_gen;

// ------------------------------- utility kernels -----------------------------
__global__ void zero_state_kernel() {
    int i = blockIdx.x * blockDim.x + threadIdx.x;
    if (i == 0) { g_bar_count = 0; g_bar_gen = 0; }
    if (i < B_SZ * H_RNN) {
        g_c[0][i] = 0.f; g_c[1][i] = 0.f;
        __half z = __float2half(0.f);
        g_hs[0][0][i] = z; g_hs[0][1][i] = z;
        g_hs[1][0][i] = z; g_hs[1][1][i] = z;
    }
}

// bias combine with gate-interleave permutation: row g*H+u -> u*4+g
__global__ void gbias_kernel(const float* __restrict__ bih0, const float* __restrict__ bhh0,
                             const float* __restrict__ bih1, const float* __restrict__ bhh1) {
    int idx = blockIdx.x * blockDim.x + threadIdx.x;
    if (idx < G4) {
        int g = idx >> 10, u = idx & 1023;
        int rp = (u << 2) | g;
        g_gb0[rp] = bih0[idx] + bhh0[idx];
        g_gb1[rp] = bih1[idx] + bhh1[idx];
    }
}

// fp32 -> fp16(x * 2^14) convert — emb (A of xp0 GEMM; emb ~2e-5 needs lift)
__global__ void convA_f16s_kernel(const float4* __restrict__ X, uint2* __restrict__ O, int n4) {
    int i = blockIdx.x * 256 + threadIdx.x;
    if (i >= n4) return;
    float4 v = X[i];
    uint2 p;
    p.x = (uint32_t)__half_as_ushort(__float2half(v.x * A_SCALE))
        | ((uint32_t)__half_as_ushort(__float2half(v.y * A_SCALE)) << 16);
    p.y = (uint32_t)__half_as_ushort(__float2half(v.z * A_SCALE))
        | ((uint32_t)__half_as_ushort(__float2half(v.w * A_SCALE)) << 16);
    O[i] = p;
}

// fp16 split + gate-interleave permute for 4096-row, K=1024 weights
__global__ void presplitW_f16_kernel(const float4* __restrict__ src, uint2* __restrict__ dh,
                                     uint2* __restrict__ dl, int dstride4, int coff4, int n4) {
    int i = blockIdx.x * 256 + threadIdx.x;
    if (i >= n4) return;
    int r0 = i >> 8, k4 = i & 255;
    int g = r0 >> 10, u = r0 & 1023;
    int rp = (u << 2) | g;
    float4 v = src[i];
    __half h0 = __float2half(v.x);
    __half h1 = __float2half(v.y);
    __half h2 = __float2half(v.z);
    __half h3 = __float2half(v.w);
    __half l0 = __float2half((v.x - __half2float(h0)) * LO_SCALE);
    __half l1 = __float2half((v.y - __half2float(h1)) * LO_SCALE);
    __half l2 = __float2half((v.z - __half2float(h2)) * LO_SCALE);
    __half l3 = __float2half((v.w - __half2float(h3)) * LO_SCALE);
    uint2 ph, pl;
    ph.x = (uint32_t)__half_as_ushort(h0) | ((uint32_t)__half_as_ushort(h1) << 16);
    ph.y = (uint32_t)__half_as_ushort(h2) | ((uint32_t)__half_as_ushort(h3) << 16);
    pl.x = (uint32_t)__half_as_ushort(l0) | ((uint32_t)__half_as_ushort(l1) << 16);
    pl.y = (uint32_t)__half_as_ushort(l2) | ((uint32_t)__half_as_ushort(l3) << 16);
    dh[(size_t)rp * dstride4 + coff4 + k4] = ph;
    dl[(size_t)rp * dstride4 + coff4 + k4] = pl;
}

// fp16 split + permute for Wih0 (K=512) -> xp0 GEMM B operand
__global__ void splitWih0_f16_perm_kernel(const float4* __restrict__ src, uint2* __restrict__ Hi,
                                          uint2* __restrict__ Lo, int n4) {
    int i = blockIdx.x * 256 + threadIdx.x;
    if (i >= n4) return;
    int r0 = i >> 7, k4 = i & 127;
    int g = r0 >> 10, u = r0 & 1023;
    int rp = (u << 2) | g;
    float4 v = src[i];
    __half h0 = __float2half(v.x);
    __half h1 = __float2half(v.y);
    __half h2 = __float2half(v.z);
    __half h3 = __float2half(v.w);
    __half l0 = __float2half((v.x - __half2float(h0)) * LO_SCALE);
    __half l1 = __float2half((v.y - __half2float(h1)) * LO_SCALE);
    __half l2 = __float2half((v.z - __half2float(h2)) * LO_SCALE);
    __half l3 = __float2half((v.w - __half2float(h3)) * LO_SCALE);
    uint2 ph, pl;
    ph.x = (uint32_t)__half_as_ushort(h0) | ((uint32_t)__half_as_ushort(h1) << 16);
    ph.y = (uint32_t)__half_as_ushort(h2) | ((uint32_t)__half_as_ushort(h3) << 16);
    pl.x = (uint32_t)__half_as_ushort(l0) | ((uint32_t)__half_as_ushort(l1) << 16);
    pl.y = (uint32_t)__half_as_ushort(l2) | ((uint32_t)__half_as_ushort(l3) << 16);
    Hi[rp * 128 + k4] = ph;
    Lo[rp * 128 + k4] = pl;
}

// fp32 -> fp16 single convert — decoder B
__global__ void convB_f16_kernel(const float4* __restrict__ X, uint2* __restrict__ O, int n4) {
    int i = blockIdx.x * 256 + threadIdx.x;
    if (i >= n4) return;
    float4 v = X[i];
    uint2 p;
    p.x = (uint32_t)__half_as_ushort(__float2half(v.x))
        | ((uint32_t)__half_as_ushort(__float2half(v.y)) << 16);
    p.y = (uint32_t)__half_as_ushort(__float2half(v.z))
        | ((uint32_t)__half_as_ushort(__float2half(v.w)) << 16);
    O[i] = p;
}

// ht / vb
__global__ void ht_kernel(const int* __restrict__ timestep,
                          const float* __restrict__ W1, const float* __restrict__ b1,
                          const float* __restrict__ W2, const float* __restrict__ b2,
                          const float* __restrict__ trans_b) {
    int b = blockIdx.x;
    int j = threadIdx.x;
    float ts = (float)timestep[b] / 100.0f;
    __shared__ float h1[D_T];
    __shared__ float hts[D_T];
    h1[j] = tanhf(ts * W1[j] + b1[j]);
    __syncthreads();
    float acc = b2[j];
    #pragma unroll 8
    for (int k = 0; k < D_T; k++) acc += W2[j * D_T + k] * h1[k];
    float htv = tanhf(acc);
    g_ht[b * D_T + j] = htv;
    hts[j] = htv;
    __syncthreads();
    float vb = 0.f;
    #pragma unroll 8
    for (int k = 0; k < D_T; k++) vb += trans_b[j * D_T + k] * hts[k];
    g_vb[b * D_T + j] = vb;
}

// M[b][i][k]; grid (64, 4, 4): z = batch group of 8
__global__ void M_kernel(const float* __restrict__ trans_W) {
    __shared__ float sht[8 * D_T];
    int bq  = blockIdx.z;
    int tid = threadIdx.x;
    for (int lin = tid; lin < 8 * D_T; lin += 128) sht[lin] = g_ht[bq * 8 * D_T + lin];
    __syncthreads();
    int i = blockIdx.x;
    int k = blockIdx.y * 128 + tid;
    float acc[8];
    #pragma unroll
    for (int b = 0; b < 8; b++) acc[b] = 0.f;
    for (int j = 0; j < D_T; j++) {
        float w = __ldg(&trans_W[(i * D_T + j) * NWE + k]);
        #pragma unroll
        for (int b = 0; b < 8; b++) acc[b] += sht[b * D_T + j] * w;
    }
    #pragma unroll
    for (int b = 0; b < 8; b++)
        g_M[((size_t)(bq * 8 + b) * D_T + i) * NWE + k] = acc[b];
}

__global__ void emb_kernel(const int* __restrict__ text, const float* __restrict__ U,
                           const float* __restrict__ dw_W, const float* __restrict__ dw_b) {
    extern __shared__ float MsT[];
    __shared__ float us[NWE];
    __shared__ float vecs[16][D_T];
    __shared__ float sp[4][D_T];
    int b   = blockIdx.x >> 3;
    int grp = blockIdx.x & 7;
    int tid = threadIdx.x;

    for (int lin = tid; lin < D_T * NWE; lin += 256) {
        int i = lin >> 9;
        int k = lin & 511;
        MsT[k * 65 + i] = g_M[(b * D_T + i) * NWE + k];
    }
    int i    = tid & 63;
    int part = tid >> 6;
    float vbv = 0.f;
    __syncthreads();
    if (part == 0) vbv = g_vb[b * D_T + i];

    for (int tt = 0; tt < 16; tt++) {
        int s = grp * 16 + tt;
        int n = s * B_SZ + b;
        int tok = text[n];
        __syncthreads();
        for (int k = tid; k < NWE; k += 256) us[k] = U[(size_t)tok * NWE + k];
        __syncthreads();
        float acc = 0.f;
        int k0 = part * 128;
        #pragma unroll 8
        for (int k = 0; k < 128; k++) acc += us[k0 + k] * MsT[(k0 + k) * 65 + i];
        sp[part][i] = acc;
        __syncthreads();
        if (part == 0) vecs[tt][i] = vbv + sp[0][i] + sp[1][i] + sp[2][i] + sp[3][i];
    }
    __syncthreads();

    float accs[16];
    for (int e = tid; e < NWE; e += 256) {
        float bias = dw_b[e];
        #pragma unroll
        for (int t = 0; t < 16; t++) accs[t] = bias;
        for (int i2 = 0; i2 < D_T; i2++) {
            float w = __ldg(&dw_W[e * D_T + i2]);
            #pragma unroll
            for (int t = 0; t < 16; t++) accs[t] += vecs[t][i2] * w;
        }
        #pragma unroll
        for (int t = 0; t < 16; t++) {
            int n = (grp * 16 + t) * B_SZ + b;
            g_emb[n * NWE + e] = accs[t];
        }
    }
}

// ================= shared GEMM machinery =====================================
#define HG_ARR   (16 * 1024)

__device__ __forceinline__ void mma_f16(float* c, const uint32_t* a, const uint32_t* b) {
    asm volatile(
        "mma.sync.aligned.m16n8k16.row.col.f32.f16.f16.f32 "
        "{%0,%1,%2,%3},{%4,%5,%6,%7},{%8,%9},{%0,%1,%2,%3};"
        : "+f"(c[0]), "+f"(c[1]), "+f"(c[2]), "+f"(c[3])
        : "r"(a[0]), "r"(a[1]), "r"(a[2]), "r"(a[3]), "r"(b[0]), "r"(b[1]));
}

__device__ __forceinline__ void ldsm4(uint32_t* r, uint32_t addr) {
    asm volatile("ldmatrix.sync.aligned.m8n8.x4.shared.b16 {%0,%1,%2,%3}, [%4];"
                 : "=r"(r[0]), "=r"(r[1]), "=r"(r[2]), "=r"(r[3]) : "r"(addr));
}

__device__ __forceinline__ void cp16(uint32_t s, const void* g) {
    asm volatile("cp.async.cg.shared.global [%0], [%1], 16;" :: "r"(s), "l"(g));
}

// ====== fp16 2-product GEMM-NT (xp0): C = A_s*(Bh + Bl/2048)/2^14 + bias =====
// A_s = fp16(emb * 2^14); B = Wih0 split fp16 hi + lo*2048 (gate-permuted).
#define HG_STAGE3 (3 * HG_ARR)
#define HG_SMEM3  (3 * HG_STAGE3)      // 144KB

__global__ __launch_bounds__(256, 1)
void gemm_f16_2p_xp0(int M, int N, int K,
                     const __half* __restrict__ As,
                     const __half* __restrict__ Bh, const __half* __restrict__ Bl,
                     const float* __restrict__ bias, float* __restrict__ C) {
    extern __shared__ __half smx[];
    const int tid  = threadIdx.x;
    const int lane = tid & 31;
    const int w    = tid >> 5;
    const int wm   = w >> 2;
    const int wn   = w & 3;
    const int bm   = blockIdx.x * 128;
    const int bn   = blockIdx.y * 128;
    const int NC   = K >> 6;

    uint32_t sbase = (uint32_t)__cvta_generic_to_shared(smx);

    auto stage = [&](int chunk) {
        int k0 = chunk << 6;
        uint32_t sb = sbase + (chunk % 3) * HG_STAGE3;
        #pragma unroll
        for (int r = 0; r < 4; r++) {
            int idx = tid + r * 256;
            int row = idx >> 3, ch = idx & 7;
            uint32_t so = (uint32_t)(row * 128 + (ch ^ (row & 7)) * 16);
            size_t ga = (size_t)(bm + row) * K + k0 + ch * 8;
            size_t gb = (size_t)(bn + row) * K + k0 + ch * 8;
            cp16(sb + 0 * HG_ARR + so, As + ga);
            cp16(sb + 1 * HG_ARR + so, Bh + gb);
            cp16(sb + 2 * HG_ARR + so, Bl + gb);
        }
        asm volatile("cp.async.commit_group;");
    };

    float acch[4][4][4], accl[4][4][4];
    #pragma unroll
    for (int mt = 0; mt < 4; mt++)
        #pragma unroll
        for (int nt = 0; nt < 4; nt++)
            #pragma unroll
            for (int e = 0; e < 4; e++) { acch[mt][nt][e] = 0.f; accl[mt][nt][e] = 0.f; }

    stage(0);
    if (NC > 1) stage(1);
    if (NC > 2) stage(2);

    const int arow = wm * 64 + (lane & 15);
    const int asel = lane >> 4;
    const int brow = wn * 32 + ((lane >> 4) << 3) + (lane & 7);
    const int bsel = (lane >> 3) & 1;

    for (int i = 0; i < NC; i++) {
        if (i + 3 <= NC - 1)      asm volatile("cp.async.wait_group 2;");
        else if (i + 2 <= NC - 1) asm volatile("cp.async.wait_group 1;");
        else                      asm volatile("cp.async.wait_group 0;");
        __syncthreads();

        uint32_t sb = sbase + (i % 3) * HG_STAGE3;
        #pragma unroll
        for (int kk = 0; kk < 4; kk++) {
            uint32_t ah[4][4];
            #pragma unroll
            for (int mt = 0; mt < 4; mt++) {
                int r = arow + mt * 16;
                uint32_t ch = (uint32_t)((kk * 2 + asel) ^ (r & 7));
                ldsm4(ah[mt], sb + r * 128 + ch * 16);
            }
            uint32_t bh[4][2], bl[4][2];
            #pragma unroll
            for (int p = 0; p < 2; p++) {
                int n = brow + p * 16;
                uint32_t ch = (uint32_t)((kk * 2 + bsel) ^ (n & 7));
                uint32_t ad = sb + 1 * HG_ARR + n * 128 + ch * 16;
                uint32_t t0[4], t1[4];
                ldsm4(t0, ad);
                ldsm4(t1, ad + HG_ARR);
                bh[2 * p][0] = t0[0]; bh[2 * p][1] = t0[1];
                bh[2 * p + 1][0] = t0[2]; bh[2 * p + 1][1] = t0[3];
                bl[2 * p][0] = t1[0]; bl[2 * p][1] = t1[1];
                bl[2 * p + 1][0] = t1[2]; bl[2 * p + 1][1] = t1[3];
            }
            #pragma unroll
            for (int mt = 0; mt < 4; mt++)
                #pragma unroll
                for (int nt = 0; nt < 4; nt++) {
                    mma_f16(acch[mt][nt], ah[mt], bh[nt]);
                    mma_f16(accl[mt][nt], ah[mt], bl[nt]);
                }
        }
        __syncthreads();
        if (i + 3 < NC) stage(i + 3);
    }

    #pragma unroll
    for (int mt = 0; mt < 4; mt++) {
        int row = bm + wm * 64 + mt * 16 + (lane >> 2);
        #pragma unroll
        for (int nt = 0; nt < 4; nt++) {
            int col = bn + wn * 32 + nt * 8 + (lane & 3) * 2;
            float2 bb = *(const float2*)&bias[col];
            float2 v0 = make_float2(
                (acch[mt][nt][0] + accl[mt][nt][0] * INV_LO_SCALE) * INV_A_SCALE + bb.x,
                (acch[mt][nt][1] + accl[mt][nt][1] * INV_LO_SCALE) * INV_A_SCALE + bb.y);
            float2 v1 = make_float2(
                (acch[mt][nt][2] + accl[mt][nt][2] * INV_LO_SCALE) * INV_A_SCALE + bb.x,
                (acch[mt][nt][3] + accl[mt][nt][3] * INV_LO_SCALE) * INV_A_SCALE + bb.y);
            *(float2*)&C[(size_t)row * N + col] = v0;
            *(float2*)&C[(size_t)(row + 8) * N + col] = v1;
        }
    }
}

// ====== fp16 1-product GEMM-NT (decoder): C = A_s * B / 2^14 + bias ==========
#define HG_STAGE2 (2 * HG_ARR)
#define HG_SMEM2  (3 * HG_STAGE2)

__global__ __launch_bounds__(256, 2)
void gemm_f16_1p(int M, int N, int K,
                 const __half* __restrict__ As, const __half* __restrict__ B,
                 const float* __restrict__ bias, float* __restrict__ C) {
    extern __shared__ __half smh[];
    const int tid  = threadIdx.x;
    const int lane = tid & 31;
    const int w    = tid >> 5;
    const int wm   = w >> 2;
    const int wn   = w & 3;
    const int bm   = blockIdx.x * 128;
    const int bn   = blockIdx.y * 128;
    const int NC   = K >> 6;

    uint32_t sbase = (uint32_t)__cvta_generic_to_shared(smh);

    auto stage = [&](int chunk) {
        int k0 = chunk << 6;
        uint32_t sb = sbase + (chunk % 3) * HG_STAGE2;
        #pragma unroll
        for (int r = 0; r < 4; r++) {
            int idx = tid + r * 256;
            int row = idx >> 3, ch = idx & 7;
            uint32_t so = (uint32_t)(row * 128 + (ch ^ (row & 7)) * 16);
            size_t ga = (size_t)(bm + row) * K + k0 + ch * 8;
            size_t gb = (size_t)(bn + row) * K + k0 + ch * 8;
            cp16(sb + 0 * HG_ARR + so, As + ga);
            cp16(sb + 1 * HG_ARR + so, B + gb);
        }
        asm volatile("cp.async.commit_group;");
    };

    float acc[4][4][4];
    #pragma unroll
    for (int mt = 0; mt < 4; mt++)
        #pragma unroll
        for (int nt = 0; nt < 4; nt++)
            #pragma unroll
            for (int e = 0; e < 4; e++) acc[mt][nt][e] = 0.f;

    stage(0);
    if (NC > 1) stage(1);
    if (NC > 2) stage(2);

    const int arow = wm * 64 + (lane & 15);
    const int asel = lane >> 4;
    const int brow = wn * 32 + ((lane >> 4) << 3) + (lane & 7);
    const int bsel = (lane >> 3) & 1;

    for (int i = 0; i < NC; i++) {
        if (i + 3 <= NC - 1)      asm volatile("cp.async.wait_group 2;");
        else if (i + 2 <= NC - 1) asm volatile("cp.async.wait_group 1;");
        else                      asm volatile("cp.async.wait_group 0;");
        __syncthreads();

        uint32_t sb = sbase + (i % 3) * HG_STAGE2;
        #pragma unroll
        for (int kk = 0; kk < 4; kk++) {
            uint32_t ah[4][4];
            #pragma unroll
            for (int mt = 0; mt < 4; mt++) {
                int r = arow + mt * 16;
                uint32_t ch = (uint32_t)((kk * 2 + asel) ^ (r & 7));
                ldsm4(ah[mt], sb + r * 128 + ch * 16);
            }
            uint32_t bf[4][2];
            #pragma unroll
            for (int p = 0; p < 2; p++) {
                int n = brow + p * 16;
                uint32_t ch = (uint32_t)((kk * 2 + bsel) ^ (n & 7));
                uint32_t t0[4];
                ldsm4(t0, sb + 1 * HG_ARR + n * 128 + ch * 16);
                bf[2 * p][0] = t0[0]; bf[2 * p][1] = t0[1];
                bf[2 * p + 1][0] = t0[2]; bf[2 * p + 1][1] = t0[3];
            }
            #pragma unroll
            for (int mt = 0; mt < 4; mt++)
                #pragma unroll
                for (int nt = 0; nt < 4; nt++)
                    mma_f16(acc[mt][nt], ah[mt], bf[nt]);
        }
        __syncthreads();
        if (i + 3 < NC) stage(i + 3);
    }

    #pragma unroll
    for (int mt = 0; mt < 4; mt++) {
        int row = bm + wm * 64 + mt * 16 + (lane >> 2);
        #pragma unroll
        for (int nt = 0; nt < 4; nt++) {
            int col = bn + wn * 32 + nt * 8 + (lane & 3) * 2;
            float2 bb = *(const float2*)&bias[col];
            float2 v0 = make_float2(acc[mt][nt][0] * INV_A_SCALE + bb.x,
                                    acc[mt][nt][1] * INV_A_SCALE + bb.y);
            float2 v1 = make_float2(acc[mt][nt][2] * INV_A_SCALE + bb.x,
                                    acc[mt][nt][3] * INV_A_SCALE + bb.y);
            *(float2*)&C[(size_t)row * N + col] = v0;
            *(float2*)&C[(size_t)(row + 8) * N + col] = v1;
        }
    }
}

// ====== persistent three-group balanced LSTM recurrence (W-prefetch) =========
// Grid 384 CTAs (3/SM). Iteration i:
//   group 0: layer0 step t=i; group 1: xp1[t=i-1]; group 2: layer1 step t=i-2.
// Weight parts of stages 0-2 are t-independent: prefetched BEFORE grid_sync
// (overlapping barrier latency); only 4KB A-parts load post-barrier.
// Wait-count analysis gives uniform cp.async.wait_group 2 across all chunks.
#define ST4_CHUNK  12288
#define ST4_RED    (8 * 16 * 36 * 4)                  // 18432
#define ST4_SMEM   (3 * ST4_CHUNK + ST4_RED)          // 55296
#define GRID_P     384

__device__ __forceinline__ void grid_sync_() {
    __syncthreads();
    if (threadIdx.x == 0) {
        __threadfence();
        unsigned int gen = g_bar_gen;
        if (atomicAdd(&g_bar_count, 1) == GRID_P - 1) {
            g_bar_count = 0;
            __threadfence();
            atomicExch(&g_bar_gen, gen + 1);
        } else {
            volatile unsigned int* vg = &g_bar_gen;
            while (*vg == gen) { }
        }
        __threadfence();
    }
    __syncthreads();
}

__global__ __launch_bounds__(256, 3)
void lstm_persistent() {
    extern __shared__ __align__(16) char sms[];
    float* red = (float*)(sms + 3 * ST4_CHUNK);
    const int bid   = blockIdx.x;
    const int group = bid >> 7;         // 0,1,2
    const int ub    = bid & 127;
    const int bn  = ub * 32;
    const int tid = threadIdx.x;
    const int lane = tid & 31;
    const int w    = tid >> 5;
    const int mt   = w & 1;
    const int kkw  = w >> 1;

    const int KB   = (group == 0) ? 1024 : 2048;
    const int woff = (group == 1) ? 1024 : 0;
    const __half* Wh = (group == 0) ? g_W0h : g_W1h;
    const __half* Wl = (group == 0) ? g_W0l : g_W1l;

    uint32_t sbase = (uint32_t)__cvta_generic_to_shared(sms);

    const int arow = mt * 16 + (lane & 15);
    const int asel = lane >> 4;
    const int brow = ((lane >> 4) << 3) + (lane & 7);
    const int bsel = (lane >> 3) & 1;

    // W-only fill of stage pc (pc in {0,1,2}): 8KB, t-independent addresses
    auto stageW = [&](int pc) {
        uint32_t sb = sbase + pc * ST4_CHUNK;
        int k0w = woff + (pc << 6);
        #pragma unroll
        for (int r = 0; r < 2; r++) {
            int s = tid + r * 256;
            int arr = 1 + (s >> 8);         // 1=Wh, 2=Wl
            int row = (s >> 3) & 31;
            int ch  = s & 7;
            uint32_t so = (uint32_t)(arr * 4096 + row * 128 + ((ch ^ (row & 7)) * 16));
            const __half* src = (arr == 1)
                ? Wh + (size_t)(bn + row) * KB + k0w + ch * 8
                : Wl + (size_t)(bn + row) * KB + k0w + ch * 8;
            cp16(sb + so, src);
        }
        asm volatile("cp.async.commit_group;");
    };
    // A-only fill of stage c (c in {0,1,2}): 4KB
    auto stageA = [&](int c, const __half* pA) {
        uint32_t sb = sbase + c * ST4_CHUNK;
        int row = tid >> 3, ch = tid & 7;
        uint32_t so = (uint32_t)(row * 128 + ((ch ^ (row & 7)) * 16));
        cp16(sb + so, pA + (size_t)row * H_RNN + (c << 6) + ch * 8);
        asm volatile("cp.async.commit_group;");
    };
    // full fill (A + W) of chunk c (stage c%3)
    auto stageF = [&](int c, const __half* pA) {
        uint32_t sb = sbase + (c % 3) * ST4_CHUNK;
        int ka  = c << 6;
        int k0w = woff + ka;
        #pragma unroll
        for (int r = 0; r < 3; r++) {
            int s = tid + r * 256;
            int arr = s >> 8;               // 0=A, 1=Wh, 2=Wl
            int row = (s >> 3) & 31;
            int ch  = s & 7;
            uint32_t so = (uint32_t)(arr * 4096 + row * 128 + ((ch ^ (row & 7)) * 16));
            const __half* src;
            if (arr == 0)      src = pA + (size_t)row * H_RNN + ka + ch * 8;
            else if (arr == 1) src = Wh + (size_t)(bn + row) * KB + k0w + ch * 8;
            else               src = Wl + (size_t)(bn + row) * KB + k0w + ch * 8;
            cp16(sb + so, src);
        }
        asm volatile("cp.async.commit_group;");
    };

    bool primed = false;
    for (int i = 0; i <= S_LEN + 1; i++) {
        const int t = i - group;        // group0: i, group1: i-1, group2: i-2
        if (t >= 0 && t < S_LEN) {
            const int parity = t & 1;
            const __half* pA;
            if (group == 0)      pA = g_hs[0][parity];
            else if (group == 1) pA = g_o0 + (size_t)t * B_SZ * H_RNN;
            else                 pA = g_hs[1][parity];

            if (!primed) { stageW(0); stageW(1); stageW(2); primed = true; }
            stageA(0, pA); stageA(1, pA); stageA(2, pA);

            float acch[4][4], accl[4][4];
            #pragma unroll
            for (int nt = 0; nt < 4; nt++)
                #pragma unroll
                for (int e = 0; e < 4; e++) { acch[nt][e] = 0.f; accl[nt][e] = 0.f; }

            for (int c = 0; c < 16; c++) {
                asm volatile("cp.async.wait_group 2;");
                __syncthreads();

                uint32_t sb = sbase + (c % 3) * ST4_CHUNK;
                uint32_t ah[4];
                {
                    uint32_t ch = (uint32_t)((kkw * 2 + asel) ^ (arow & 7));
                    ldsm4(ah, sb + arow * 128 + ch * 16);
                }
                uint32_t bh[4][2], bl[4][2];
                #pragma unroll
                for (int p = 0; p < 2; p++) {
                    int n = brow + p * 16;
                    uint32_t ch = (uint32_t)((kkw * 2 + bsel) ^ (n & 7));
                    uint32_t ad = sb + 4096 + n * 128 + ch * 16;
                    uint32_t t0[4], t1[4];
                    ldsm4(t0, ad);
                    ldsm4(t1, ad + 4096);
                    bh[2 * p][0] = t0[0]; bh[2 * p][1] = t0[1];
                    bh[2 * p + 1][0] = t0[2]; bh[2 * p + 1][1] = t0[3];
                    bl[2 * p][0] = t1[0]; bl[2 * p][1] = t1[1];
                    bl[2 * p + 1][0] = t1[2]; bl[2 * p + 1][1] = t1[3];
                }
                #pragma unroll
                for (int nt = 0; nt < 4; nt++) {
                    mma_f16(acch[nt], ah, bh[nt]);
                    mma_f16(accl[nt], ah, bl[nt]);
                }
                __syncthreads();
                if (c + 3 < 16) stageF(c + 3, pA);
                else            stageW(c % 3);      // W prefetch for next iter
            }

            // partials: combine hi + lo/2048 before reduction write
            float* rw = red + w * (16 * 36);
            #pragma unroll
            for (int nt = 0; nt < 4; nt++) {
                int r0 = lane >> 2;
                int cl = nt * 8 + (lane & 3) * 2;
                rw[r0 * 36 + cl]           = acch[nt][0] + accl[nt][0] * INV_LO_SCALE;
                rw[r0 * 36 + cl + 1]       = acch[nt][1] + accl[nt][1] * INV_LO_SCALE;
                rw[(r0 + 8) * 36 + cl]     = acch[nt][2] + accl[nt][2] * INV_LO_SCALE;
                rw[(r0 + 8) * 36 + cl + 1] = acch[nt][3] + accl[nt][3] * INV_LO_SCALE;
            }
            __syncthreads();

            // reduce over kkw; thread = (b, unit-local)
            int b   = tid >> 3;
            int ul  = tid & 7;
            int mtb = b >> 4;
            int rl  = b & 15;
            float4 s = make_float4(0.f, 0.f, 0.f, 0.f);
            #pragma unroll
            for (int k2 = 0; k2 < 4; k2++) {
                float4 v = *(float4*)&red[(k2 * 2 + mtb) * (16 * 36) + rl * 36 + ul * 4];
                s.x += v.x; s.y += v.y; s.z += v.z; s.w += v.w;
            }
            s.x *= INV_A_SCALE; s.y *= INV_A_SCALE; s.z *= INV_A_SCALE; s.w *= INV_A_SCALE;
            int colg = bn + ul * 4;

            if (group == 1) {
                float4 x = *(const float4*)&g_gb1[colg];
                s.x += x.x; s.y += x.y; s.z += x.z; s.w += x.w;
                *(float4*)&g_xp1g[parity][b * G4 + colg] = s;
            } else {
                if (group == 0) {
                    float4 x = *(const float4*)&g_xp0[(size_t)t * B_SZ * G4 + (size_t)b * G4 + colg];
                    s.x += x.x; s.y += x.y; s.z += x.z; s.w += x.w;
                } else {
                    float4 x = *(const float4*)&g_xp1g[parity][b * G4 + colg];
                    s.x += x.x; s.y += x.y; s.z += x.z; s.w += x.w;
                }
                int layer = (group == 0) ? 0 : 1;
                float I = 1.f / (1.f + __expf(-s.x));
                float F = 1.f / (1.f + __expf(-s.y));
                float G = tanhf(s.z);
                float O = 1.f / (1.f + __expf(-s.w));
                int u   = ub * 8 + ul;
                int idx = b * H_RNN + u;
                float cv = F * g_c[layer][idx] + I * G;
                g_c[layer][idx] = cv;
                float hv = O * tanhf(cv);
                __half hsc = __float2half(hv * A_SCALE);
                g_hs[layer][parity ^ 1][idx] = hsc;
                if (layer == 0) {
                    g_o0[(size_t)t * B_SZ * H_RNN + idx] = hsc;
                } else {
                    g_Ah[(size_t)(t * B_SZ + b) * H_RNN + u] = hsc;
                }
            }
        }
        grid_sync_();
    }
}

// --------------------------------- launcher ----------------------------------
extern "C" void kernel_launch(void* const* d_in, const int* in_sizes, int n_in,
                              void* d_out, int out_size) {
    const int*   text     = (const int*)d_in[0];
    const int*   timestep = (const int*)d_in[1];
    const float* U        = (const float*)d_in[2];
    const float* trans_W  = (const float*)d_in[3];
    const float* trans_b  = (const float*)d_in[4];
    const float* tc_W1    = (const float*)d_in[5];
    const float* tc_b1    = (const float*)d_in[6];
    const float* tc_W2    = (const float*)d_in[7];
    const float* tc_b2    = (const float*)d_in[8];
    const float* dw_W     = (const float*)d_in[9];
    const float* dw_b     = (const float*)d_in[10];
    const float* Wih0     = (const float*)d_in[11];
    const float* Whh0     = (const float*)d_in[12];
    const float* bih0     = (const float*)d_in[13];
    const float* bhh0     = (const float*)d_in[14];
    const float* Wih1     = (const float*)d_in[15];
    const float* Whh1     = (const float*)d_in[16];
    const float* bih1     = (const float*)d_in[17];
    const float* bhh1     = (const float*)d_in[18];
    const float* dec_W    = (const float*)d_in[19];
    const float* dec_b    = (const float*)d_in[20];
    float* out = (float*)d_out;

    float *p_emb, *p_xp0, *p_gb0;
    __half *p_Ah, *p_Bh, *p_Bl, *p_W0h, *p_W0l, *p_W1h, *p_W1l;
    cudaGetSymbolAddress((void**)&p_emb, g_emb);
    cudaGetSymbolAddress((void**)&p_xp0, g_xp0);
    cudaGetSymbolAddress((void**)&p_gb0, g_gb0);
    cudaGetSymbolAddress((void**)&p_Ah,  g_Ah);
    cudaGetSymbolAddress((void**)&p_Bh,  g_Bh);
    cudaGetSymbolAddress((void**)&p_Bl,  g_Bl);
    cudaGetSymbolAddress((void**)&p_W0h, g_W0h);
    cudaGetSymbolAddress((void**)&p_W0l, g_W0l);
    cudaGetSymbolAddress((void**)&p_W1h, g_W1h);
    cudaGetSymbolAddress((void**)&p_W1l, g_W1l);

    cudaFuncSetAttribute(emb_kernel, cudaFuncAttributeMaxDynamicSharedMemorySize, 512 * 65 * 4);
    cudaFuncSetAttribute(lstm_persistent, cudaFuncAttributeMaxDynamicSharedMemorySize, ST4_SMEM);
    cudaFuncSetAttribute(gemm_f16_2p_xp0, cudaFuncAttributeMaxDynamicSharedMemorySize, HG_SMEM3);
    cudaFuncSetAttribute(gemm_f16_1p, cudaFuncAttributeMaxDynamicSharedMemorySize, HG_SMEM2);

    zero_state_kernel<<<(B_SZ * H_RNN + 255) / 256, 256>>>();
    gbias_kernel<<<(G4 + 255) / 256, 256>>>(bih0, bhh0, bih1, bhh1);
    ht_kernel<<<B_SZ, D_T>>>(timestep, tc_W1, tc_b1, tc_W2, tc_b2, trans_b);
    M_kernel<<<dim3(D_T, 4, 4), 128>>>(trans_W);
    emb_kernel<<<256, 256, 512 * 65 * 4>>>(text, U, dw_W, dw_b);

    // weight pre-splits (fp16 hi + lo*2048, gate-interleaved), once per replay
    int n4w = G4 * 256;
    presplitW_f16_kernel<<<(n4w + 255) / 256, 256>>>((const float4*)Whh0, (uint2*)p_W0h, (uint2*)p_W0l, 256, 0, n4w);
    presplitW_f16_kernel<<<(n4w + 255) / 256, 256>>>((const float4*)Whh1, (uint2*)p_W1h, (uint2*)p_W1l, 512, 0, n4w);
    presplitW_f16_kernel<<<(n4w + 255) / 256, 256>>>((const float4*)Wih1, (uint2*)p_W1h, (uint2*)p_W1l, 512, 256, n4w);

    int n4;
    // xp0 = emb @ Wih0p^T + gb0p   [4096 x 4096 permuted cols], K=512
    // fp16 2-product: A = fp16(emb*2^14), B = Wih0 split fp16 hi + lo*2048
    n4 = NTOKR * NWE / 4;
    convA_f16s_kernel<<<(n4 + 255) / 256, 256>>>((const float4*)p_emb, (uint2*)p_Ah, n4);
    n4 = G4 * NWE / 4;
    splitWih0_f16_perm_kernel<<<(n4 + 255) / 256, 256>>>((const float4*)Wih0, (uint2*)p_Bh, (uint2*)p_Bl, n4);
    gemm_f16_2p_xp0<<<dim3(NTOKR / 128, G4 / 128), 256, HG_SMEM3>>>(
        NTOKR, G4, NWE, p_Ah, p_Bh, p_Bl, p_gb0, p_xp0);

    // persistent balanced recurrence: one launch, internal grid barriers
    lstm_persistent<<<GRID_P, 256, ST4_SMEM>>>();

    // logits = out1 @ dec_W^T + dec_b  (decoder A written by layer1 epilogue)
    n4 = NVOCAB * H_RNN / 4;
    convB_f16_kernel<<<(n4 + 255) / 256, 256>>>((const float4*)dec_W, (uint2*)p_Bh, n4);
    gemm_f16_1p<<<dim3(NTOKR / 128, NVOCAB / 128), 256, HG_SMEM2>>>(
        NTOKR, NVOCAB, H_RNN, p_Ah, p_Bh, dec_b, out);
}

// round 17
// speedup vs baseline: 1.0255x; 1.0255x over previous
#include <cuda_runtime.h>
#include <cuda_bf16.h>
#include <cuda_fp16.h>
#include <math.h>
#include <stdint.h>

#define S_LEN  128
#define B_SZ   32
#define NTOKR  4096      // S*B rows
#define NWE    512
#define D_T    64
#define H_RNN  1024
#define G4     4096      // 4*H
#define NVOCAB 32000

#define A_SCALE       16384.0f          // 2^14: lifts tiny activations into fp16 normal range
#define INV_A_SCALE   6.103515625e-5f
#define LO_SCALE      2048.0f
#define INV_LO_SCALE  4.8828125e-4f

// ------------------- scratch (device globals; no allocs allowed) -------------
__device__ float g_ht[B_SZ * D_T];
__device__ float g_vb[B_SZ * D_T];
__device__ float g_M[B_SZ * D_T * NWE];          // 4MB
__device__ float g_emb[NTOKR * NWE];             // 8MB
__device__ float g_xp0[(size_t)NTOKR * G4];      // 64MB (PERMUTED gate cols)
__device__ float g_xp1g[2][B_SZ * G4];           // ping-pong layer1 input gates (1MB)
__device__ float g_c[2][B_SZ * H_RNN];
__device__ float g_gb0[G4];                      // permuted
__device__ float g_gb1[G4];                      // permuted
// fp16 scratch (g_Ah: emb*2^14 for xp0 A, later decoder A written by layer1;
// g_Bh/g_Bl: Wih0 split for xp0 B, later g_Bh = decoder fp16 B)
__device__ __half g_Ah[(size_t)NTOKR * H_RNN];               // 8MB
__device__ __half g_Bh[(size_t)NVOCAB * H_RNN];              // 62.5MB
__device__ __half g_Bl[(size_t)NVOCAB * H_RNN];              // 62.5MB
// LSTM tensorized state: fp16 split weights (permuted rows), fp16 scaled h/out0
__device__ __half g_W0h[(size_t)G4 * H_RNN];                 // 8MB
__device__ __half g_W0l[(size_t)G4 * H_RNN];
__device__ __half g_W1h[(size_t)G4 * 2048];                  // 16MB ([Whh1|Wih1])
__device__ __half g_W1l[(size_t)G4 * 2048];
__device__ __half g_hs[2][2][B_SZ * H_RNN];                  // h * 2^14
__device__ __half g_o0[(size_t)NTOKR * H_RNN];               // out0 * 2^14, 8MB
// persistent-kernel grid barrier state
__device__ unsigned int g_bar_count;
__device__ unsigned int g_bar_gen;

// ------------------------------- utility kernels -----------------------------
__global__ void zero_state_kernel() {
    int i = blockIdx.x * blockDim.x + threadIdx.x;
    if (i == 0) { g_bar_count = 0; g_bar_gen = 0; }
    if (i < B_SZ * H_RNN) {
        g_c[0][i] = 0.f; g_c[1][i] = 0.f;
        __half z = __float2half(0.f);
        g_hs[0][0][i] = z; g_hs[0][1][i] = z;
        g_hs[1][0][i] = z; g_hs[1][1][i] = z;
    }
}

// bias combine with gate-interleave permutation: row g*H+u -> u*4+g
__global__ void gbias_kernel(const float* __restrict__ bih0, const float* __restrict__ bhh0,
                             const float* __restrict__ bih1, const float* __restrict__ bhh1) {
    int idx = blockIdx.x * blockDim.x + threadIdx.x;
    if (idx < G4) {
        int g = idx >> 10, u = idx & 1023;
        int rp = (u << 2) | g;
        g_gb0[rp] = bih0[idx] + bhh0[idx];
        g_gb1[rp] = bih1[idx] + bhh1[idx];
    }
}

// fp32 -> fp16(x * 2^14) convert — emb (A of xp0 GEMM; emb ~2e-5 needs lift)
__global__ void convA_f16s_kernel(const float4* __restrict__ X, uint2* __restrict__ O, int n4) {
    int i = blockIdx.x * 256 + threadIdx.x;
    if (i >= n4) return;
    float4 v = X[i];
    uint2 p;
    p.x = (uint32_t)__half_as_ushort(__float2half(v.x * A_SCALE))
        | ((uint32_t)__half_as_ushort(__float2half(v.y * A_SCALE)) << 16);
    p.y = (uint32_t)__half_as_ushort(__float2half(v.z * A_SCALE))
        | ((uint32_t)__half_as_ushort(__float2half(v.w * A_SCALE)) << 16);
    O[i] = p;
}

// fp16 split + gate-interleave permute for 4096-row, K=1024 weights
__global__ void presplitW_f16_kernel(const float4* __restrict__ src, uint2* __restrict__ dh,
                                     uint2* __restrict__ dl, int dstride4, int coff4, int n4) {
    int i = blockIdx.x * 256 + threadIdx.x;
    if (i >= n4) return;
    int r0 = i >> 8, k4 = i & 255;
    int g = r0 >> 10, u = r0 & 1023;
    int rp = (u << 2) | g;
    float4 v = src[i];
    __half h0 = __float2half(v.x);
    __half h1 = __float2half(v.y);
    __half h2 = __float2half(v.z);
    __half h3 = __float2half(v.w);
    __half l0 = __float2half((v.x - __half2float(h0)) * LO_SCALE);
    __half l1 = __float2half((v.y - __half2float(h1)) * LO_SCALE);
    __half l2 = __float2half((v.z - __half2float(h2)) * LO_SCALE);
    __half l3 = __float2half((v.w - __half2float(h3)) * LO_SCALE);
    uint2 ph, pl;
    ph.x = (uint32_t)__half_as_ushort(h0) | ((uint32_t)__half_as_ushort(h1) << 16);
    ph.y = (uint32_t)__half_as_ushort(h2) | ((uint32_t)__half_as_ushort(h3) << 16);
    pl.x = (uint32_t)__half_as_ushort(l0) | ((uint32_t)__half_as_ushort(l1) << 16);
    pl.y = (uint32_t)__half_as_ushort(l2) | ((uint32_t)__half_as_ushort(l3) << 16);
    dh[(size_t)rp * dstride4 + coff4 + k4] = ph;
    dl[(size_t)rp * dstride4 + coff4 + k4] = pl;
}

// fp16 split + permute for Wih0 (K=512) -> xp0 GEMM B operand
__global__ void splitWih0_f16_perm_kernel(const float4* __restrict__ src, uint2* __restrict__ Hi,
                                          uint2* __restrict__ Lo, int n4) {
    int i = blockIdx.x * 256 + threadIdx.x;
    if (i >= n4) return;
    int r0 = i >> 7, k4 = i & 127;
    int g = r0 >> 10, u = r0 & 1023;
    int rp = (u << 2) | g;
    float4 v = src[i];
    __half h0 = __float2half(v.x);
    __half h1 = __float2half(v.y);
    __half h2 = __float2half(v.z);
    __half h3 = __float2half(v.w);
    __half l0 = __float2half((v.x - __half2float(h0)) * LO_SCALE);
    __half l1 = __float2half((v.y - __half2float(h1)) * LO_SCALE);
    __half l2 = __float2half((v.z - __half2float(h2)) * LO_SCALE);
    __half l3 = __float2half((v.w - __half2float(h3)) * LO_SCALE);
    uint2 ph, pl;
    ph.x = (uint32_t)__half_as_ushort(h0) | ((uint32_t)__half_as_ushort(h1) << 16);
    ph.y = (uint32_t)__half_as_ushort(h2) | ((uint32_t)__half_as_ushort(h3) << 16);
    pl.x = (uint32_t)__half_as_ushort(l0) | ((uint32_t)__half_as_ushort(l1) << 16);
    pl.y = (uint32_t)__half_as_ushort(l2) | ((uint32_t)__half_as_ushort(l3) << 16);
    Hi[rp * 128 + k4] = ph;
    Lo[rp * 128 + k4] = pl;
}

// fp32 -> fp16 single convert — decoder B
__global__ void convB_f16_kernel(const float4* __restrict__ X, uint2* __restrict__ O, int n4) {
    int i = blockIdx.x * 256 + threadIdx.x;
    if (i >= n4) return;
    float4 v = X[i];
    uint2 p;
    p.x = (uint32_t)__half_as_ushort(__float2half(v.x))
        | ((uint32_t)__half_as_ushort(__float2half(v.y)) << 16);
    p.y = (uint32_t)__half_as_ushort(__float2half(v.z))
        | ((uint32_t)__half_as_ushort(__float2half(v.w)) << 16);
    O[i] = p;
}

// ht / vb
__global__ void ht_kernel(const int* __restrict__ timestep,
                          const float* __restrict__ W1, const float* __restrict__ b1,
                          const float* __restrict__ W2, const float* __restrict__ b2,
                          const float* __restrict__ trans_b) {
    int b = blockIdx.x;
    int j = threadIdx.x;
    float ts = (float)timestep[b] / 100.0f;
    __shared__ float h1[D_T];
    __shared__ float hts[D_T];
    h1[j] = tanhf(ts * W1[j] + b1[j]);
    __syncthreads();
    float acc = b2[j];
    #pragma unroll 8
    for (int k = 0; k < D_T; k++) acc += W2[j * D_T + k] * h1[k];
    float htv = tanhf(acc);
    g_ht[b * D_T + j] = htv;
    hts[j] = htv;
    __syncthreads();
    float vb = 0.f;
    #pragma unroll 8
    for (int k = 0; k < D_T; k++) vb += trans_b[j * D_T + k] * hts[k];
    g_vb[b * D_T + j] = vb;
}

// M[b][i][k]; grid (64, 4, 4): z = batch group of 8
__global__ void M_kernel(const float* __restrict__ trans_W) {
    __shared__ float sht[8 * D_T];
    int bq  = blockIdx.z;
    int tid = threadIdx.x;
    for (int lin = tid; lin < 8 * D_T; lin += 128) sht[lin] = g_ht[bq * 8 * D_T + lin];
    __syncthreads();
    int i = blockIdx.x;
    int k = blockIdx.y * 128 + tid;
    float acc[8];
    #pragma unroll
    for (int b = 0; b < 8; b++) acc[b] = 0.f;
    for (int j = 0; j < D_T; j++) {
        float w = __ldg(&trans_W[(i * D_T + j) * NWE + k]);
        #pragma unroll
        for (int b = 0; b < 8; b++) acc[b] += sht[b * D_T + j] * w;
    }
    #pragma unroll
    for (int b = 0; b < 8; b++)
        g_M[((size_t)(bq * 8 + b) * D_T + i) * NWE + k] = acc[b];
}

__global__ void emb_kernel(const int* __restrict__ text, const float* __restrict__ U,
                           const float* __restrict__ dw_W, const float* __restrict__ dw_b) {
    extern __shared__ float MsT[];
    __shared__ float us[NWE];
    __shared__ float vecs[16][D_T];
    __shared__ float sp[4][D_T];
    int b   = blockIdx.x >> 3;
    int grp = blockIdx.x & 7;
    int tid = threadIdx.x;

    for (int lin = tid; lin < D_T * NWE; lin += 256) {
        int i = lin >> 9;
        int k = lin & 511;
        MsT[k * 65 + i] = g_M[(b * D_T + i) * NWE + k];
    }
    int i    = tid & 63;
    int part = tid >> 6;
    float vbv = 0.f;
    __syncthreads();
    if (part == 0) vbv = g_vb[b * D_T + i];

    for (int tt = 0; tt < 16; tt++) {
        int s = grp * 16 + tt;
        int n = s * B_SZ + b;
        int tok = text[n];
        __syncthreads();
        for (int k = tid; k < NWE; k += 256) us[k] = U[(size_t)tok * NWE + k];
        __syncthreads();
        float acc = 0.f;
        int k0 = part * 128;
        #pragma unroll 8
        for (int k = 0; k < 128; k++) acc += us[k0 + k] * MsT[(k0 + k) * 65 + i];
        sp[part][i] = acc;
        __syncthreads();
        if (part == 0) vecs[tt][i] = vbv + sp[0][i] + sp[1][i] + sp[2][i] + sp[3][i];
    }
    __syncthreads();

    float accs[16];
    for (int e = tid; e < NWE; e += 256) {
        float bias = dw_b[e];
        #pragma unroll
        for (int t = 0; t < 16; t++) accs[t] = bias;
        for (int i2 = 0; i2 < D_T; i2++) {
            float w = __ldg(&dw_W[e * D_T + i2]);
            #pragma unroll
            for (int t = 0; t < 16; t++) accs[t] += vecs[t][i2] * w;
        }
        #pragma unroll
        for (int t = 0; t < 16; t++) {
            int n = (grp * 16 + t) * B_SZ + b;
            g_emb[n * NWE + e] = accs[t];
        }
    }
}

// ================= shared GEMM machinery =====================================
#define HG_ARR   (16 * 1024)

__device__ __forceinline__ void mma_f16(float* c, const uint32_t* a, const uint32_t* b) {
    asm volatile(
        "mma.sync.aligned.m16n8k16.row.col.f32.f16.f16.f32 "
        "{%0,%1,%2,%3},{%4,%5,%6,%7},{%8,%9},{%0,%1,%2,%3};"
        : "+f"(c[0]), "+f"(c[1]), "+f"(c[2]), "+f"(c[3])
        : "r"(a[0]), "r"(a[1]), "r"(a[2]), "r"(a[3]), "r"(b[0]), "r"(b[1]));
}

__device__ __forceinline__ void ldsm4(uint32_t* r, uint32_t addr) {
    asm volatile("ldmatrix.sync.aligned.m8n8.x4.shared.b16 {%0,%1,%2,%3}, [%4];"
                 : "=r"(r[0]), "=r"(r[1]), "=r"(r[2]), "=r"(r[3]) : "r"(addr));
}

__device__ __forceinline__ void cp16(uint32_t s, const void* g) {
    asm volatile("cp.async.cg.shared.global [%0], [%1], 16;" :: "r"(s), "l"(g));
}

// ====== fp16 2-product GEMM-NT (xp0): C = A_s*(Bh + Bl/2048)/2^14 + bias =====
// A_s = fp16(emb * 2^14); B = Wih0 split fp16 hi + lo*2048 (gate-permuted).
#define HG_STAGE3 (3 * HG_ARR)
#define HG_SMEM3  (3 * HG_STAGE3)      // 144KB

__global__ __launch_bounds__(256, 1)
void gemm_f16_2p_xp0(int M, int N, int K,
                     const __half* __restrict__ As,
                     const __half* __restrict__ Bh, const __half* __restrict__ Bl,
                     const float* __restrict__ bias, float* __restrict__ C) {
    extern __shared__ __half smx[];
    const int tid  = threadIdx.x;
    const int lane = tid & 31;
    const int w    = tid >> 5;
    const int wm   = w >> 2;
    const int wn   = w & 3;
    const int bm   = blockIdx.x * 128;
    const int bn   = blockIdx.y * 128;
    const int NC   = K >> 6;

    uint32_t sbase = (uint32_t)__cvta_generic_to_shared(smx);

    auto stage = [&](int chunk) {
        int k0 = chunk << 6;
        uint32_t sb = sbase + (chunk % 3) * HG_STAGE3;
        #pragma unroll
        for (int r = 0; r < 4; r++) {
            int idx = tid + r * 256;
            int row = idx >> 3, ch = idx & 7;
            uint32_t so = (uint32_t)(row * 128 + (ch ^ (row & 7)) * 16);
            size_t ga = (size_t)(bm + row) * K + k0 + ch * 8;
            size_t gb = (size_t)(bn + row) * K + k0 + ch * 8;
            cp16(sb + 0 * HG_ARR + so, As + ga);
            cp16(sb + 1 * HG_ARR + so, Bh + gb);
            cp16(sb + 2 * HG_ARR + so, Bl + gb);
        }
        asm volatile("cp.async.commit_group;");
    };

    float acch[4][4][4], accl[4][4][4];
    #pragma unroll
    for (int mt = 0; mt < 4; mt++)
        #pragma unroll
        for (int nt = 0; nt < 4; nt++)
            #pragma unroll
            for (int e = 0; e < 4; e++) { acch[mt][nt][e] = 0.f; accl[mt][nt][e] = 0.f; }

    stage(0);
    if (NC > 1) stage(1);
    if (NC > 2) stage(2);

    const int arow = wm * 64 + (lane & 15);
    const int asel = lane >> 4;
    const int brow = wn * 32 + ((lane >> 4) << 3) + (lane & 7);
    const int bsel = (lane >> 3) & 1;

    for (int i = 0; i < NC; i++) {
        if (i + 3 <= NC - 1)      asm volatile("cp.async.wait_group 2;");
        else if (i + 2 <= NC - 1) asm volatile("cp.async.wait_group 1;");
        else                      asm volatile("cp.async.wait_group 0;");
        __syncthreads();

        uint32_t sb = sbase + (i % 3) * HG_STAGE3;
        #pragma unroll
        for (int kk = 0; kk < 4; kk++) {
            uint32_t ah[4][4];
            #pragma unroll
            for (int mt = 0; mt < 4; mt++) {
                int r = arow + mt * 16;
                uint32_t ch = (uint32_t)((kk * 2 + asel) ^ (r & 7));
                ldsm4(ah[mt], sb + r * 128 + ch * 16);
            }
            uint32_t bh[4][2], bl[4][2];
            #pragma unroll
            for (int p = 0; p < 2; p++) {
                int n = brow + p * 16;
                uint32_t ch = (uint32_t)((kk * 2 + bsel) ^ (n & 7));
                uint32_t ad = sb + 1 * HG_ARR + n * 128 + ch * 16;
                uint32_t t0[4], t1[4];
                ldsm4(t0, ad);
                ldsm4(t1, ad + HG_ARR);
                bh[2 * p][0] = t0[0]; bh[2 * p][1] = t0[1];
                bh[2 * p + 1][0] = t0[2]; bh[2 * p + 1][1] = t0[3];
                bl[2 * p][0] = t1[0]; bl[2 * p][1] = t1[1];
                bl[2 * p + 1][0] = t1[2]; bl[2 * p + 1][1] = t1[3];
            }
            #pragma unroll
            for (int mt = 0; mt < 4; mt++)
                #pragma unroll
                for (int nt = 0; nt < 4; nt++) {
                    mma_f16(acch[mt][nt], ah[mt], bh[nt]);
                    mma_f16(accl[mt][nt], ah[mt], bl[nt]);
                }
        }
        __syncthreads();
        if (i + 3 < NC) stage(i + 3);
    }

    #pragma unroll
    for (int mt = 0; mt < 4; mt++) {
        int row = bm + wm * 64 + mt * 16 + (lane >> 2);
        #pragma unroll
        for (int nt = 0; nt < 4; nt++) {
            int col = bn + wn * 32 + nt * 8 + (lane & 3) * 2;
            float2 bb = *(const float2*)&bias[col];
            float2 v0 = make_float2(
                (acch[mt][nt][0] + accl[mt][nt][0] * INV_LO_SCALE) * INV_A_SCALE + bb.x,
                (acch[mt][nt][1] + accl[mt][nt][1] * INV_LO_SCALE) * INV_A_SCALE + bb.y);
            float2 v1 = make_float2(
                (acch[mt][nt][2] + accl[mt][nt][2] * INV_LO_SCALE) * INV_A_SCALE + bb.x,
                (acch[mt][nt][3] + accl[mt][nt][3] * INV_LO_SCALE) * INV_A_SCALE + bb.y);
            *(float2*)&C[(size_t)row * N + col] = v0;
            *(float2*)&C[(size_t)(row + 8) * N + col] = v1;
        }
    }
}

// ====== fp16 1-product GEMM-NT (decoder): C = A_s * B / 2^14 + bias ==========
#define HG_STAGE2 (2 * HG_ARR)
#define HG_SMEM2  (3 * HG_STAGE2)

__global__ __launch_bounds__(256, 2)
void gemm_f16_1p(int M, int N, int K,
                 const __half* __restrict__ As, const __half* __restrict__ B,
                 const float* __restrict__ bias, float* __restrict__ C) {
    extern __shared__ __half smh[];
    const int tid  = threadIdx.x;
    const int lane = tid & 31;
    const int w    = tid >> 5;
    const int wm   = w >> 2;
    const int wn   = w & 3;
    const int bm   = blockIdx.x * 128;
    const int bn   = blockIdx.y * 128;
    const int NC   = K >> 6;

    uint32_t sbase = (uint32_t)__cvta_generic_to_shared(smh);

    auto stage = [&](int chunk) {
        int k0 = chunk << 6;
        uint32_t sb = sbase + (chunk % 3) * HG_STAGE2;
        #pragma unroll
        for (int r = 0; r < 4; r++) {
            int idx = tid + r * 256;
            int row = idx >> 3, ch = idx & 7;
            uint32_t so = (uint32_t)(row * 128 + (ch ^ (row & 7)) * 16);
            size_t ga = (size_t)(bm + row) * K + k0 + ch * 8;
            size_t gb = (size_t)(bn + row) * K + k0 + ch * 8;
            cp16(sb + 0 * HG_ARR + so, As + ga);
            cp16(sb + 1 * HG_ARR + so, B + gb);
        }
        asm volatile("cp.async.commit_group;");
    };

    float acc[4][4][4];
    #pragma unroll
    for (int mt = 0; mt < 4; mt++)
        #pragma unroll
        for (int nt = 0; nt < 4; nt++)
            #pragma unroll
            for (int e = 0; e < 4; e++) acc[mt][nt][e] = 0.f;

    stage(0);
    if (NC > 1) stage(1);
    if (NC > 2) stage(2);

    const int arow = wm * 64 + (lane & 15);
    const int asel = lane >> 4;
    const int brow = wn * 32 + ((lane >> 4) << 3) + (lane & 7);
    const int bsel = (lane >> 3) & 1;

    for (int i = 0; i < NC; i++) {
        if (i + 3 <= NC - 1)      asm volatile("cp.async.wait_group 2;");
        else if (i + 2 <= NC - 1) asm volatile("cp.async.wait_group 1;");
        else                      asm volatile("cp.async.wait_group 0;");
        __syncthreads();

        uint32_t sb = sbase + (i % 3) * HG_STAGE2;
        #pragma unroll
        for (int kk = 0; kk < 4; kk++) {
            uint32_t ah[4][4];
            #pragma unroll
            for (int mt = 0; mt < 4; mt++) {
                int r = arow + mt * 16;
                uint32_t ch = (uint32_t)((kk * 2 + asel) ^ (r & 7));
                ldsm4(ah[mt], sb + r * 128 + ch * 16);
            }
            uint32_t bf[4][2];
            #pragma unroll
            for (int p = 0; p < 2; p++) {
                int n = brow + p * 16;
                uint32_t ch = (uint32_t)((kk * 2 + bsel) ^ (n & 7));
                uint32_t t0[4];
                ldsm4(t0, sb + 1 * HG_ARR + n * 128 + ch * 16);
                bf[2 * p][0] = t0[0]; bf[2 * p][1] = t0[1];
                bf[2 * p + 1][0] = t0[2]; bf[2 * p + 1][1] = t0[3];
            }
            #pragma unroll
            for (int mt = 0; mt < 4; mt++)
                #pragma unroll
                for (int nt = 0; nt < 4; nt++)
                    mma_f16(acc[mt][nt], ah[mt], bf[nt]);
        }
        __syncthreads();
        if (i + 3 < NC) stage(i + 3);
    }

    #pragma unroll
    for (int mt = 0; mt < 4; mt++) {
        int row = bm + wm * 64 + mt * 16 + (lane >> 2);
        #pragma unroll
        for (int nt = 0; nt < 4; nt++) {
            int col = bn + wn * 32 + nt * 8 + (lane & 3) * 2;
            float2 bb = *(const float2*)&bias[col];
            float2 v0 = make_float2(acc[mt][nt][0] * INV_A_SCALE + bb.x,
                                    acc[mt][nt][1] * INV_A_SCALE + bb.y);
            float2 v1 = make_float2(acc[mt][nt][2] * INV_A_SCALE + bb.x,
                                    acc[mt][nt][3] * INV_A_SCALE + bb.y);
            *(float2*)&C[(size_t)row * N + col] = v0;
            *(float2*)&C[(size_t)(row + 8) * N + col] = v1;
        }
    }
}

// ====== persistent three-group balanced LSTM recurrence (round-15 body) ======
// Grid 384 CTAs (3/SM). Iteration i:
//   group 0: layer0 step t=i; group 1: xp1[t=i-1]; group 2: layer1 step t=i-2.
// One homogeneous 12KB commit-group per chunk; 2/1/0 wait schedule (proven).
#define ST4_CHUNK  12288
#define ST4_RED    (8 * 16 * 36 * 4)                  // 18432
#define ST4_SMEM   (3 * ST4_CHUNK + ST4_RED)          // 55296
#define GRID_P     384

__device__ __forceinline__ void grid_sync_() {
    __syncthreads();
    if (threadIdx.x == 0) {
        __threadfence();
        unsigned int gen = g_bar_gen;
        if (atomicAdd(&g_bar_count, 1) == GRID_P - 1) {
            g_bar_count = 0;
            __threadfence();
            atomicExch(&g_bar_gen, gen + 1);
        } else {
            volatile unsigned int* vg = &g_bar_gen;
            while (*vg == gen) { }
        }
        __threadfence();
    }
    __syncthreads();
}

__global__ __launch_bounds__(256, 3)
void lstm_persistent() {
    extern __shared__ __align__(16) char sms[];
    float* red = (float*)(sms + 3 * ST4_CHUNK);
    const int bid   = blockIdx.x;
    const int group = bid >> 7;         // 0,1,2
    const int ub    = bid & 127;
    const int bn  = ub * 32;
    const int tid = threadIdx.x;
    const int lane = tid & 31;
    const int w    = tid >> 5;
    const int mt   = w & 1;
    const int kkw  = w >> 1;

    const int KB   = (group == 0) ? 1024 : 2048;
    const int woff = (group == 1) ? 1024 : 0;
    const __half* Wh = (group == 0) ? g_W0h : g_W1h;
    const __half* Wl = (group == 0) ? g_W0l : g_W1l;

    uint32_t sbase = (uint32_t)__cvta_generic_to_shared(sms);

    const int arow = mt * 16 + (lane & 15);
    const int asel = lane >> 4;
    const int brow = ((lane >> 4) << 3) + (lane & 7);
    const int bsel = (lane >> 3) & 1;

    for (int i = 0; i <= S_LEN + 1; i++) {
        const int t = i - group;        // group0: i, group1: i-1, group2: i-2
        if (t >= 0 && t < S_LEN) {
            const int parity = t & 1;
            const __half* pA;
            if (group == 0)      pA = g_hs[0][parity];
            else if (group == 1) pA = g_o0 + (size_t)t * B_SZ * H_RNN;
            else                 pA = g_hs[1][parity];

            auto stage = [&](int c) {
                uint32_t sb = sbase + (c % 3) * ST4_CHUNK;
                int ka  = c << 6;
                int k0w = woff + ka;
                #pragma unroll
                for (int r = 0; r < 3; r++) {
                    int s = tid + r * 256;
                    int arr = s >> 8;               // 0=A, 1=Wh, 2=Wl
                    int row = (s >> 3) & 31;
                    int ch  = s & 7;
                    uint32_t so = (uint32_t)(arr * 4096 + row * 128 + ((ch ^ (row & 7)) * 16));
                    const __half* src;
                    if (arr == 0)      src = pA + (size_t)row * H_RNN + ka + ch * 8;
                    else if (arr == 1) src = Wh + (size_t)(bn + row) * KB + k0w + ch * 8;
                    else               src = Wl + (size_t)(bn + row) * KB + k0w + ch * 8;
                    cp16(sb + so, src);
                }
                asm volatile("cp.async.commit_group;");
            };

            float acch[4][4], accl[4][4];
            #pragma unroll
            for (int nt = 0; nt < 4; nt++)
                #pragma unroll
                for (int e = 0; e < 4; e++) { acch[nt][e] = 0.f; accl[nt][e] = 0.f; }

            stage(0);
            stage(1);
            stage(2);

            for (int c = 0; c < 16; c++) {
                if (c + 3 <= 15)      asm volatile("cp.async.wait_group 2;");
                else if (c + 2 <= 15) asm volatile("cp.async.wait_group 1;");
                else                  asm volatile("cp.async.wait_group 0;");
                __syncthreads();

                uint32_t sb = sbase + (c % 3) * ST4_CHUNK;
                uint32_t ah[4];
                {
                    uint32_t ch = (uint32_t)((kkw * 2 + asel) ^ (arow & 7));
                    ldsm4(ah, sb + arow * 128 + ch * 16);
                }
                uint32_t bh[4][2], bl[4][2];
                #pragma unroll
                for (int p = 0; p < 2; p++) {
                    int n = brow + p * 16;
                    uint32_t ch = (uint32_t)((kkw * 2 + bsel) ^ (n & 7));
                    uint32_t ad = sb + 4096 + n * 128 + ch * 16;
                    uint32_t t0[4], t1[4];
                    ldsm4(t0, ad);
                    ldsm4(t1, ad + 4096);
                    bh[2 * p][0] = t0[0]; bh[2 * p][1] = t0[1];
                    bh[2 * p + 1][0] = t0[2]; bh[2 * p + 1][1] = t0[3];
                    bl[2 * p][0] = t1[0]; bl[2 * p][1] = t1[1];
                    bl[2 * p + 1][0] = t1[2]; bl[2 * p + 1][1] = t1[3];
                }
                #pragma unroll
                for (int nt = 0; nt < 4; nt++) {
                    mma_f16(acch[nt], ah, bh[nt]);
                    mma_f16(accl[nt], ah, bl[nt]);
                }
                __syncthreads();
                if (c + 3 < 16) stage(c + 3);
            }

            // partials: combine hi + lo/2048 before reduction write
            float* rw = red + w * (16 * 36);
            #pragma unroll
            for (int nt = 0; nt < 4; nt++) {
                int r0 = lane >> 2;
                int cl = nt * 8 + (lane & 3) * 2;
                rw[r0 * 36 + cl]           = acch[nt][0] + accl[nt][0] * INV_LO_SCALE;
                rw[r0 * 36 + cl + 1]       = acch[nt][1] + accl[nt][1] * INV_LO_SCALE;
                rw[(r0 + 8) * 36 + cl]     = acch[nt][2] + accl[nt][2] * INV_LO_SCALE;
                rw[(r0 + 8) * 36 + cl + 1] = acch[nt][3] + accl[nt][3] * INV_LO_SCALE;
            }
            __syncthreads();

            // reduce over kkw; thread = (b, unit-local)
            int b   = tid >> 3;
            int ul  = tid & 7;
            int mtb = b >> 4;
            int rl  = b & 15;
            float4 s = make_float4(0.f, 0.f, 0.f, 0.f);
            #pragma unroll
            for (int k2 = 0; k2 < 4; k2++) {
                float4 v = *(float4*)&red[(k2 * 2 + mtb) * (16 * 36) + rl * 36 + ul * 4];
                s.x += v.x; s.y += v.y; s.z += v.z; s.w += v.w;
            }
            s.x *= INV_A_SCALE; s.y *= INV_A_SCALE; s.z *= INV_A_SCALE; s.w *= INV_A_SCALE;
            int colg = bn + ul * 4;

            if (group == 1) {
                float4 x = *(const float4*)&g_gb1[colg];
                s.x += x.x; s.y += x.y; s.z += x.z; s.w += x.w;
                *(float4*)&g_xp1g[parity][b * G4 + colg] = s;
            } else {
                if (group == 0) {
                    float4 x = *(const float4*)&g_xp0[(size_t)t * B_SZ * G4 + (size_t)b * G4 + colg];
                    s.x += x.x; s.y += x.y; s.z += x.z; s.w += x.w;
                } else {
                    float4 x = *(const float4*)&g_xp1g[parity][b * G4 + colg];
                    s.x += x.x; s.y += x.y; s.z += x.z; s.w += x.w;
                }
                int layer = (group == 0) ? 0 : 1;
                float I = 1.f / (1.f + __expf(-s.x));
                float F = 1.f / (1.f + __expf(-s.y));
                float G = tanhf(s.z);
                float O = 1.f / (1.f + __expf(-s.w));
                int u   = ub * 8 + ul;
                int idx = b * H_RNN + u;
                float cv = F * g_c[layer][idx] + I * G;
                g_c[layer][idx] = cv;
                float hv = O * tanhf(cv);
                __half hsc = __float2half(hv * A_SCALE);
                g_hs[layer][parity ^ 1][idx] = hsc;
                if (layer == 0) {
                    g_o0[(size_t)t * B_SZ * H_RNN + idx] = hsc;
                } else {
                    g_Ah[(size_t)(t * B_SZ + b) * H_RNN + u] = hsc;
                }
            }
        }
        grid_sync_();
    }
}

// --------------------------------- launcher ----------------------------------
extern "C" void kernel_launch(void* const* d_in, const int* in_sizes, int n_in,
                              void* d_out, int out_size) {
    const int*   text     = (const int*)d_in[0];
    const int*   timestep = (const int*)d_in[1];
    const float* U        = (const float*)d_in[2];
    const float* trans_W  = (const float*)d_in[3];
    const float* trans_b  = (const float*)d_in[4];
    const float* tc_W1    = (const float*)d_in[5];
    const float* tc_b1    = (const float*)d_in[6];
    const float* tc_W2    = (const float*)d_in[7];
    const float* tc_b2    = (const float*)d_in[8];
    const float* dw_W     = (const float*)d_in[9];
    const float* dw_b     = (const float*)d_in[10];
    const float* Wih0     = (const float*)d_in[11];
    const float* Whh0     = (const float*)d_in[12];
    const float* bih0     = (const float*)d_in[13];
    const float* bhh0     = (const float*)d_in[14];
    const float* Wih1     = (const float*)d_in[15];
    const float* Whh1     = (const float*)d_in[16];
    const float* bih1     = (const float*)d_in[17];
    const float* bhh1     = (const float*)d_in[18];
    const float* dec_W    = (const float*)d_in[19];
    const float* dec_b    = (const float*)d_in[20];
    float* out = (float*)d_out;

    float *p_emb, *p_xp0, *p_gb0;
    __half *p_Ah, *p_Bh, *p_Bl, *p_W0h, *p_W0l, *p_W1h, *p_W1l;
    cudaGetSymbolAddress((void**)&p_emb, g_emb);
    cudaGetSymbolAddress((void**)&p_xp0, g_xp0);
    cudaGetSymbolAddress((void**)&p_gb0, g_gb0);
    cudaGetSymbolAddress((void**)&p_Ah,  g_Ah);
    cudaGetSymbolAddress((void**)&p_Bh,  g_Bh);
    cudaGetSymbolAddress((void**)&p_Bl,  g_Bl);
    cudaGetSymbolAddress((void**)&p_W0h, g_W0h);
    cudaGetSymbolAddress((void**)&p_W0l, g_W0l);
    cudaGetSymbolAddress((void**)&p_W1h, g_W1h);
    cudaGetSymbolAddress((void**)&p_W1l, g_W1l);

    cudaFuncSetAttribute(emb_kernel, cudaFuncAttributeMaxDynamicSharedMemorySize, 512 * 65 * 4);
    cudaFuncSetAttribute(lstm_persistent, cudaFuncAttributeMaxDynamicSharedMemorySize, ST4_SMEM);
    cudaFuncSetAttribute(gemm_f16_2p_xp0, cudaFuncAttributeMaxDynamicSharedMemorySize, HG_SMEM3);
    cudaFuncSetAttribute(gemm_f16_1p, cudaFuncAttributeMaxDynamicSharedMemorySize, HG_SMEM2);

    zero_state_kernel<<<(B_SZ * H_RNN + 255) / 256, 256>>>();
    gbias_kernel<<<(G4 + 255) / 256, 256>>>(bih0, bhh0, bih1, bhh1);
    ht_kernel<<<B_SZ, D_T>>>(timestep, tc_W1, tc_b1, tc_W2, tc_b2, trans_b);
    M_kernel<<<dim3(D_T, 4, 4), 128>>>(trans_W);
    emb_kernel<<<256, 256, 512 * 65 * 4>>>(text, U, dw_W, dw_b);

    // weight pre-splits (fp16 hi + lo*2048, gate-interleaved), once per replay
    int n4w = G4 * 256;
    presplitW_f16_kernel<<<(n4w + 255) / 256, 256>>>((const float4*)Whh0, (uint2*)p_W0h, (uint2*)p_W0l, 256, 0, n4w);
    presplitW_f16_kernel<<<(n4w + 255) / 256, 256>>>((const float4*)Whh1, (uint2*)p_W1h, (uint2*)p_W1l, 512, 0, n4w);
    presplitW_f16_kernel<<<(n4w + 255) / 256, 256>>>((const float4*)Wih1, (uint2*)p_W1h, (uint2*)p_W1l, 512, 256, n4w);

    int n4;
    // xp0 = emb @ Wih0p^T + gb0p   [4096 x 4096 permuted cols], K=512
    // fp16 2-product: A = fp16(emb*2^14), B = Wih0 split fp16 hi + lo*2048
    n4 = NTOKR * NWE / 4;
    convA_f16s_kernel<<<(n4 + 255) / 256, 256>>>((const float4*)p_emb, (uint2*)p_Ah, n4);
    n4 = G4 * NWE / 4;
    splitWih0_f16_perm_kernel<<<(n4 + 255) / 256, 256>>>((const float4*)Wih0, (uint2*)p_Bh, (uint2*)p_Bl, n4);
    gemm_f16_2p_xp0<<<dim3(NTOKR / 128, G4 / 128), 256, HG_SMEM3>>>(
        NTOKR, G4, NWE, p_Ah, p_Bh, p_Bl, p_gb0, p_xp0);

    // persistent balanced recurrence: one launch, internal grid barriers
    lstm_persistent<<<GRID_P, 256, ST4_SMEM>>>();

    // logits = out1 @ dec_W^T + dec_b  (decoder A written by layer1 epilogue)
    n4 = NVOCAB * H_RNN / 4;
    convB_f16_kernel<<<(n4 + 255) / 256, 256>>>((const float4*)dec_W, (uint2*)p_Bh, n4);
    gemm_f16_1p<<<dim3(NTOKR / 128, NVOCAB / 128), 256, HG_SMEM2>>>(
        NTOKR, NVOCAB, H_RNN, p_Ah, p_Bh, dec_b, out);
}